// round 4
// baseline (speedup 1.0000x reference)
#include <cuda_runtime.h>
#include <cuda_bf16.h>
#include <stdint.h>

// Problem constants
#define BB   4
#define H    352
#define W    1216
#define HW   (H*W)               // 428032
#define NPX  (BB*HW)             // 1712128 pixels
#define PAD  2
#define HP   (H + 2*PAD)         // 356
#define WP   (W + 2*PAD)         // 1220
#define NPAD (BB*HP*WP)          // 1737280
#define PROP 18

// Scratch (device globals; no allocation allowed)
__device__ float g_buf[2][NPAD];          // padded ping-pong feat buffers (conf-folded)
__device__ uint2 d_meta[8 * NPX];         // per non-center tap: (padded idx, fy|fx<<16)
__device__ float d_aff[9 * NPX];          // affinity per tap (plane 4 = center)

// ---------------------------------------------------------------------------
__global__ void zero_kernel() {
    int i = blockIdx.x * blockDim.x + threadIdx.x;
    if (i < 2 * NPAD) (&g_buf[0][0])[i] = 0.0f;
}

__global__ void init_kernel(const float* __restrict__ feat,
                            const float* __restrict__ conf) {
    int p = blockIdx.x * blockDim.x + threadIdx.x;
    if (p >= NPX) return;
    int b = p / HW;
    int r = p - b * HW;
    int y = r / W;
    int x = r - y * W;
    int pidx = (b * HP + y + PAD) * WP + (x + PAD);
    g_buf[0][pidx] = feat[p] * conf[p];
}

// ---------------------------------------------------------------------------
// Conv(8 -> 24, 3x3, pad 1) + offset/affinity epilogue; 2 pixels / thread.
__device__ __forceinline__ void write_meta(int p, int b, int y, int x,
                                           const float* acc, float inv_scale) {
    // acc[0..15] = offset channels (dy_k = acc[2k], dx_k = acc[2k+1]),
    // acc[16..23] = raw affinity
    float a[8];
    float s = 0.0f;
#pragma unroll
    for (int k = 0; k < 8; k++) {
        a[k] = tanhf(acc[16 + k]) * inv_scale;
        s += fabsf(a[k]);
    }
    s += 1e-4f;
    if (s < 1.0f) s = 1.0f;
    float invs = 1.0f / s;
    float sum = 0.0f;
#pragma unroll
    for (int k = 0; k < 8; k++) { a[k] *= invs; sum += a[k]; }
    d_aff[4 * NPX + p] = 1.0f - sum;   // reference tap affinity

#pragma unroll
    for (int j = 0; j < 9; j++) {
        if (j == 4) continue;
        int k  = (j < 4) ? j : j - 1;  // meta plane index == k
        float dy = acc[2 * k];
        float dx = acc[2 * k + 1];
        float ys = (float)(y + j / 3 - 1) + dy;
        float xs = (float)(x + j % 3 - 1) + dx;
        float y0f = floorf(ys);
        float x0f = floorf(xs);
        float fy = ys - y0f;
        float fx = xs - x0f;
        int iy = (int)fmaxf(fminf(y0f, 1.0e6f), -1.0e6f);
        int ix = (int)fmaxf(fminf(x0f, 1.0e6f), -1.0e6f);
        // clamp into padded box; out-of-image corners land on guaranteed zeros
        int yp = min(max(iy + PAD, 0), HP - 2);
        int xp = min(max(ix + PAD, 0), WP - 2);
        unsigned idx = (unsigned)((b * HP + yp) * WP + xp);
        int fu = (int)(fy * 65536.0f + 0.5f); if (fu > 65535) fu = 65535; if (fu < 0) fu = 0;
        int fv = (int)(fx * 65536.0f + 0.5f); if (fv > 65535) fv = 65535; if (fv < 0) fv = 0;
        d_meta[k * NPX + p] = make_uint2(idx, (unsigned)fu | ((unsigned)fv << 16));
        d_aff[j * NPX + p] = a[k];
    }
}

__global__ void conv_meta_kernel(const float* __restrict__ guid,
                                 const float* __restrict__ w_oa,
                                 const float* __restrict__ b_oa,
                                 const float* __restrict__ aff_scale) {
    __shared__ float ws[1728];
    __shared__ float bs[24];
    for (int i = threadIdx.x; i < 1728; i += blockDim.x) ws[i] = w_oa[i];
    if (threadIdx.x < 24) bs[threadIdx.x] = b_oa[threadIdx.x];
    __syncthreads();

    int t  = blockIdx.x * blockDim.x + threadIdx.x;
    int p0 = 2 * t;
    if (p0 >= NPX) return;
    int b = p0 / HW;
    int r = p0 - b * HW;
    int y = r / W;
    int x = r - y * W;   // x is even; x+1 in same row (W even)

    float acc0[24], acc1[24];
#pragma unroll
    for (int c = 0; c < 24; c++) { acc0[c] = bs[c]; acc1[c] = bs[c]; }

    const float* gb = guid + (size_t)b * 8 * HW;
    for (int i = 0; i < 8; i++) {
        const float* gch = gb + i * HW;
#pragma unroll
        for (int u = 0; u < 3; u++) {
            int yy = y + u - 1;
            bool yv = (yy >= 0) && (yy < H);
            const float* grow = gch + yy * W;
            float v[4];
#pragma unroll
            for (int q = 0; q < 4; q++) {
                int xx = x + q - 1;
                v[q] = (yv && xx >= 0 && xx < W) ? grow[xx] : 0.0f;
            }
#pragma unroll
            for (int kx = 0; kx < 3; kx++) {
#pragma unroll
                for (int c = 0; c < 24; c++) {
                    float w = ws[c * 72 + i * 9 + u * 3 + kx];
                    acc0[c] = fmaf(v[kx],     w, acc0[c]);
                    acc1[c] = fmaf(v[kx + 1], w, acc1[c]);
                }
            }
        }
    }

    float inv_scale = 1.0f / (aff_scale[0] + 1e-8f);
    write_meta(p0,     b, y, x,     acc0, inv_scale);
    write_meta(p0 + 1, b, y, x + 1, acc1, inv_scale);
}

// ---------------------------------------------------------------------------
// One propagation step: out = A * g_in ; store conf*out (or raw on last step).
__global__ void iter_kernel(const float* __restrict__ conf,
                            float* __restrict__ out, int sel, int last) {
    int p = blockIdx.x * blockDim.x + threadIdx.x;
    if (p >= NPX) return;
    const float* __restrict__ gin = g_buf[sel];
    int b = p / HW;
    int r = p - b * HW;
    int y = r / W;
    int x = r - y * W;
    int center = (b * HP + y + PAD) * WP + (x + PAD);

    float acc = d_aff[4 * NPX + p] * gin[center];
#pragma unroll
    for (int jj = 0; jj < 8; jj++) {
        int j = (jj < 4) ? jj : jj + 1;
        uint2 m  = d_meta[jj * NPX + p];
        float av = d_aff[j * NPX + p];
        float fy = (float)(m.y & 0xFFFFu) * (1.0f / 65536.0f);
        float fx = (float)(m.y >> 16)     * (1.0f / 65536.0f);
        const float* gp = gin + m.x;
        float f00 = gp[0];
        float f01 = gp[1];
        float f10 = gp[WP];
        float f11 = gp[WP + 1];
        float top = fmaf(fx, f01 - f00, f00);
        float bot = fmaf(fx, f11 - f10, f10);
        acc = fmaf(av, fmaf(fy, bot - top, top), acc);
    }
    if (last) out[p] = acc;
    else      g_buf[sel ^ 1][center] = conf[p] * acc;
}

// ---------------------------------------------------------------------------
extern "C" void kernel_launch(void* const* d_in, const int* in_sizes, int n_in,
                              void* d_out, int out_size) {
    const float* feat = (const float*)d_in[0];
    const float* guid = (const float*)d_in[1];
    const float* conf = (const float*)d_in[2];
    const float* w    = (const float*)d_in[3];
    const float* bia  = (const float*)d_in[4];
    const float* sc   = (const float*)d_in[5];
    float* out = (float*)d_out;

    const int thr = 256;
    zero_kernel<<<(2 * NPAD + thr - 1) / thr, thr>>>();
    init_kernel<<<(NPX + thr - 1) / thr, thr>>>(feat, conf);
    conv_meta_kernel<<<(NPX / 2 + thr - 1) / thr, thr>>>(guid, w, bia, sc);
    for (int t = 0; t < PROP; t++) {
        iter_kernel<<<(NPX + thr - 1) / thr, thr>>>(conf, out, t & 1, t == PROP - 1);
    }
}

// round 5
// speedup vs baseline: 1.2321x; 1.2321x over previous
#include <cuda_runtime.h>
#include <cuda_bf16.h>
#include <stdint.h>

// Problem constants
#define BB   4
#define H    352
#define W    1216
#define HW   (H*W)               // 428032
#define NPX  (BB*HW)             // 1712128 pixels
#define PAD  2
#define HP   (H + 2*PAD)         // 356
#define WP   (W + 2*PAD)         // 1220
#define NPAD (BB*HP*WP)          // 1737280 < 2^21
#define PROP 18

// Packed tap record (u64):
//  [0,21)  : padded linear index of top-left corner
//  [21,33) : fy  (12-bit fraction, /4096)
//  [33,45) : fx  (12-bit fraction, /4096)
//  [45,61) : aff (16-bit fixed point, (q-32768)/16384)
// Stored as 4 planes of uint4 (two taps per 16B record) for LDG.128.

__device__ float g_buf[2][NPAD];          // padded ping-pong feat (conf-folded)
__device__ uint4 d_meta[4 * NPX];         // 4 planes x (2 taps) per pixel

// ---------------------------------------------------------------------------
__global__ void zero_kernel() {
    int i = blockIdx.x * blockDim.x + threadIdx.x;
    if (i < 2 * NPAD) (&g_buf[0][0])[i] = 0.0f;
}

__global__ void init_kernel(const float* __restrict__ feat,
                            const float* __restrict__ conf) {
    int p = blockIdx.x * blockDim.x + threadIdx.x;
    if (p >= NPX) return;
    int b = p / HW;
    int r = p - b * HW;
    int y = r / W;
    int x = r - y * W;
    int pidx = (b * HP + y + PAD) * WP + (x + PAD);
    g_buf[0][pidx] = feat[p] * conf[p];
}

// ---------------------------------------------------------------------------
// Conv(8 -> 24, 3x3, pad 1) + offset/affinity epilogue; 2 pixels / thread.
__device__ __forceinline__ unsigned long long encode_tap(
        int b, int y, int x, int j, float dy, float dx, float aff)
{
    float ys = (float)(y + j / 3 - 1) + dy;
    float xs = (float)(x + j % 3 - 1) + dx;
    float y0f = floorf(ys);
    float x0f = floorf(xs);
    float fy = ys - y0f;
    float fx = xs - x0f;
    int iy = (int)fmaxf(fminf(y0f, 1.0e6f), -1.0e6f);
    int ix = (int)fmaxf(fminf(x0f, 1.0e6f), -1.0e6f);
    // clamp into padded box; out-of-image corners land on guaranteed zeros
    int yp = min(max(iy + PAD, 0), HP - 2);
    int xp = min(max(ix + PAD, 0), WP - 2);
    unsigned long long idx = (unsigned long long)((b * HP + yp) * WP + xp);
    int fu = (int)(fy * 4096.0f + 0.5f); fu = min(max(fu, 0), 4095);
    int fv = (int)(fx * 4096.0f + 0.5f); fv = min(max(fv, 0), 4095);
    int qa = (int)floorf(aff * 16384.0f + 0.5f) + 32768;
    qa = min(max(qa, 0), 65535);
    return idx | ((unsigned long long)fu << 21)
               | ((unsigned long long)fv << 33)
               | ((unsigned long long)qa << 45);
}

__device__ __forceinline__ void write_meta(int p, int b, int y, int x,
                                           const float* acc, float inv_scale) {
    // acc[0..15] = offsets (dy_k = acc[2k], dx_k = acc[2k+1]), acc[16..23] = raw aff
    float a[8];
    float s = 0.0f;
#pragma unroll
    for (int k = 0; k < 8; k++) {
        a[k] = tanhf(acc[16 + k]) * inv_scale;
        s += fabsf(a[k]);
    }
    s += 1e-4f;
    if (s < 1.0f) s = 1.0f;
    float invs = 1.0f / s;
#pragma unroll
    for (int k = 0; k < 8; k++) a[k] *= invs;

    unsigned long long rec[8];
#pragma unroll
    for (int j = 0; j < 9; j++) {
        if (j == 4) continue;
        int k = (j < 4) ? j : j - 1;
        rec[k] = encode_tap(b, y, x, j, acc[2 * k], acc[2 * k + 1], a[k]);
    }
#pragma unroll
    for (int q = 0; q < 4; q++) {
        unsigned long long m0 = rec[2 * q], m1 = rec[2 * q + 1];
        d_meta[q * NPX + p] = make_uint4((unsigned)m0, (unsigned)(m0 >> 32),
                                         (unsigned)m1, (unsigned)(m1 >> 32));
    }
}

__global__ void conv_meta_kernel(const float* __restrict__ guid,
                                 const float* __restrict__ w_oa,
                                 const float* __restrict__ b_oa,
                                 const float* __restrict__ aff_scale) {
    __shared__ float ws[1728];
    __shared__ float bs[24];
    for (int i = threadIdx.x; i < 1728; i += blockDim.x) ws[i] = w_oa[i];
    if (threadIdx.x < 24) bs[threadIdx.x] = b_oa[threadIdx.x];
    __syncthreads();

    int t  = blockIdx.x * blockDim.x + threadIdx.x;
    int p0 = 2 * t;
    if (p0 >= NPX) return;
    int b = p0 / HW;
    int r = p0 - b * HW;
    int y = r / W;
    int x = r - y * W;   // x is even; x+1 in same row (W even)

    float acc0[24], acc1[24];
#pragma unroll
    for (int c = 0; c < 24; c++) { acc0[c] = bs[c]; acc1[c] = bs[c]; }

    const float* gb = guid + (size_t)b * 8 * HW;
    for (int i = 0; i < 8; i++) {
        const float* gch = gb + i * HW;
#pragma unroll
        for (int u = 0; u < 3; u++) {
            int yy = y + u - 1;
            bool yv = (yy >= 0) && (yy < H);
            const float* grow = gch + yy * W;
            float v[4];
#pragma unroll
            for (int q = 0; q < 4; q++) {
                int xx = x + q - 1;
                v[q] = (yv && xx >= 0 && xx < W) ? grow[xx] : 0.0f;
            }
#pragma unroll
            for (int kx = 0; kx < 3; kx++) {
#pragma unroll
                for (int c = 0; c < 24; c++) {
                    float w = ws[c * 72 + i * 9 + u * 3 + kx];
                    acc0[c] = fmaf(v[kx],     w, acc0[c]);
                    acc1[c] = fmaf(v[kx + 1], w, acc1[c]);
                }
            }
        }
    }

    float inv_scale = 1.0f / (aff_scale[0] + 1e-8f);
    write_meta(p0,     b, y, x,     acc0, inv_scale);
    write_meta(p0 + 1, b, y, x + 1, acc1, inv_scale);
}

// ---------------------------------------------------------------------------
// One propagation step. Center affinity = 1 - sum(decoded tap affs): row sum
// of the operator is exactly 1 regardless of quantization.
__device__ __forceinline__ void apply_tap(const float* __restrict__ gin,
                                          unsigned long long m,
                                          float& acc, float& asum) {
    unsigned idx = (unsigned)(m & 0x1FFFFFull);
    float fy = (float)((unsigned)(m >> 21) & 0xFFFu) * (1.0f / 4096.0f);
    float fx = (float)((unsigned)(m >> 33) & 0xFFFu) * (1.0f / 4096.0f);
    float av = (float)((int)((unsigned)(m >> 45) & 0xFFFFu) - 32768)
               * (1.0f / 16384.0f);
    const float* gp = gin + idx;
    float f00 = gp[0];
    float f01 = gp[1];
    float f10 = gp[WP];
    float f11 = gp[WP + 1];
    float top = fmaf(fx, f01 - f00, f00);
    float bot = fmaf(fx, f11 - f10, f10);
    acc  = fmaf(av, fmaf(fy, bot - top, top), acc);
    asum += av;
}

__global__ void iter_kernel(const float* __restrict__ conf,
                            float* __restrict__ out, int sel, int last) {
    int p = blockIdx.x * blockDim.x + threadIdx.x;
    if (p >= NPX) return;
    const float* __restrict__ gin = g_buf[sel];
    int b = p / HW;
    int r = p - b * HW;
    int y = r / W;
    int x = r - y * W;
    int center = (b * HP + y + PAD) * WP + (x + PAD);

    float acc = 0.0f, asum = 0.0f;
#pragma unroll
    for (int q = 0; q < 4; q++) {
        uint4 mm = d_meta[q * NPX + p];
        unsigned long long m0 = (unsigned long long)mm.x
                              | ((unsigned long long)mm.y << 32);
        unsigned long long m1 = (unsigned long long)mm.z
                              | ((unsigned long long)mm.w << 32);
        apply_tap(gin, m0, acc, asum);
        apply_tap(gin, m1, acc, asum);
    }
    float v = fmaf(1.0f - asum, gin[center], acc);
    if (last) out[p] = v;
    else      g_buf[sel ^ 1][center] = conf[p] * v;
}

// ---------------------------------------------------------------------------
extern "C" void kernel_launch(void* const* d_in, const int* in_sizes, int n_in,
                              void* d_out, int out_size) {
    const float* feat = (const float*)d_in[0];
    const float* guid = (const float*)d_in[1];
    const float* conf = (const float*)d_in[2];
    const float* w    = (const float*)d_in[3];
    const float* bia  = (const float*)d_in[4];
    const float* sc   = (const float*)d_in[5];
    float* out = (float*)d_out;

    const int thr = 256;
    zero_kernel<<<(2 * NPAD + thr - 1) / thr, thr>>>();
    init_kernel<<<(NPX + thr - 1) / thr, thr>>>(feat, conf);
    conv_meta_kernel<<<(NPX / 2 + thr - 1) / thr, thr>>>(guid, w, bia, sc);
    for (int t = 0; t < PROP; t++) {
        iter_kernel<<<(NPX + thr - 1) / thr, thr>>>(conf, out, t & 1, t == PROP - 1);
    }
}